// round 7
// baseline (speedup 1.0000x reference)
#include <cuda_runtime.h>
#include <cuda_bf16.h>
#include <math.h>
#include <cstdint>

#define B_ 2
#define W_ 2048
#define C_ 1024
#define N_ 16
#define K_ 64
#define HEADS (B_*N_)

__device__ float g_P [B_*N_*W_*K_];     // P in [b][n][w][k] layout
__device__ float g_M [HEADS*K_*K_];     // mm per head
__device__ float g_Mp[HEADS*8*K_*K_];   // mbuild partials
__device__ float g_Ng[B_*W_*C_];        // nudged in [b][w][c] layout

__device__ __nv_bfloat16 g_Ahi[(size_t)B_*W_*C_];
__device__ __nv_bfloat16 g_Alo[(size_t)B_*W_*C_];
__device__ __nv_bfloat16 g_Bhi[(size_t)C_*C_];
__device__ __nv_bfloat16 g_Blo[(size_t)C_*C_];

// P transposed per head [head][k][w], pre-split once (prep_kernel)
__device__ float        g_PThi[(size_t)HEADS*K_*W_];   // tf32 hi (as fp32 bits)
__device__ float        g_PTlo[(size_t)HEADS*K_*W_];   // tf32 lo
__device__ __nv_bfloat16 g_PTbh[(size_t)HEADS*K_*W_];  // bf16 hi
__device__ __nv_bfloat16 g_PTbl[(size_t)HEADS*K_*W_];  // bf16 lo

// ---------------- helpers (plain sm_80-class PTX only) ----------------
__device__ __forceinline__ uint32_t smem_u32(const void* p) {
    uint32_t a;
    asm("{ .reg .u64 t; cvta.to.shared.u64 t, %1; cvt.u32.u64 %0, t; }" : "=r"(a) : "l"(p));
    return a;
}
__device__ __forceinline__ void ldsm_x4(uint32_t* r, uint32_t addr) {
    asm volatile("ldmatrix.sync.aligned.m8n8.x4.shared.b16 {%0,%1,%2,%3}, [%4];"
        : "=r"(r[0]), "=r"(r[1]), "=r"(r[2]), "=r"(r[3]) : "r"(addr));
}
__device__ __forceinline__ void ldsm_x2(uint32_t* r, uint32_t addr) {
    asm volatile("ldmatrix.sync.aligned.m8n8.x2.shared.b16 {%0,%1}, [%2];"
        : "=r"(r[0]), "=r"(r[1]) : "r"(addr));
}
__device__ __forceinline__ void mma_bf16(float* d, const uint32_t* a, const uint32_t* b) {
    asm volatile("mma.sync.aligned.m16n8k16.row.col.f32.bf16.bf16.f32 "
        "{%0,%1,%2,%3}, {%4,%5,%6,%7}, {%8,%9}, {%0,%1,%2,%3};"
        : "+f"(d[0]), "+f"(d[1]), "+f"(d[2]), "+f"(d[3])
        : "r"(a[0]), "r"(a[1]), "r"(a[2]), "r"(a[3]), "r"(b[0]), "r"(b[1]));
}
__device__ __forceinline__ void mma_tf32(float* d, const uint32_t* a, const uint32_t* b) {
    asm volatile("mma.sync.aligned.m16n8k8.row.col.f32.tf32.tf32.f32 "
        "{%0,%1,%2,%3}, {%4,%5,%6,%7}, {%8,%9}, {%0,%1,%2,%3};"
        : "+f"(d[0]), "+f"(d[1]), "+f"(d[2]), "+f"(d[3])
        : "r"(a[0]), "r"(a[1]), "r"(a[2]), "r"(a[3]), "r"(b[0]), "r"(b[1]));
}
__device__ __forceinline__ uint32_t f2tf32(float f) {
    uint32_t u; asm("cvt.rna.tf32.f32 %0, %1;" : "=r"(u) : "f"(f)); return u;
}
__device__ __forceinline__ void split_bf16x2(float x, float y, uint32_t& h, uint32_t& l) {
    __nv_bfloat16 hx = __float2bfloat16(x), hy = __float2bfloat16(y);
    __nv_bfloat16 lx = __float2bfloat16(x - __bfloat162float(hx));
    __nv_bfloat16 ly = __float2bfloat16(y - __bfloat162float(hy));
    __nv_bfloat162 hh = __halves2bfloat162(hx, hy);
    __nv_bfloat162 ll = __halves2bfloat162(lx, ly);
    h = *(uint32_t*)&hh; l = *(uint32_t*)&ll;
}

// ---------------------------------------------------------------------------
// fp32 -> (bf16 hi, bf16 lo)
// ---------------------------------------------------------------------------
__global__ __launch_bounds__(256)
void convert_kernel(const float* __restrict__ src, __nv_bfloat16* __restrict__ hi,
                    __nv_bfloat16* __restrict__ lo, int n4) {
    const int i = blockIdx.x * blockDim.x + threadIdx.x;
    if (i >= n4) return;
    const float4 v = ((const float4*)src)[i];
    uint32_t h0, l0, h1, l1;
    split_bf16x2(v.x, v.y, h0, l0);
    split_bf16x2(v.z, v.w, h1, l1);
    ((uint32_t*)hi)[i*2+0] = h0; ((uint32_t*)hi)[i*2+1] = h1;
    ((uint32_t*)lo)[i*2+0] = l0; ((uint32_t*)lo)[i*2+1] = l1;
}

// ---------------------------------------------------------------------------
// prep: per head transpose P [w][k] -> [k][w], split tf32 hi/lo + bf16 hi/lo
// grid (32 w-tiles, 32 heads), 256 threads
// ---------------------------------------------------------------------------
__global__ __launch_bounds__(256)
void prep_kernel() {
    __shared__ __align__(16) float ts[64*65];
    const int t = threadIdx.x;
    const int bn = blockIdx.y;
    const int w0 = blockIdx.x * 64;
    const float* Pp = g_P + (size_t)bn*W_*K_;
    {
        const int r  = t >> 2;          // w row 0..63
        const int c0 = (t & 3) * 16;    // k base
        const float* src = Pp + (size_t)(w0 + r)*K_ + c0;
        #pragma unroll
        for (int q = 0; q < 4; q++) {
            const float4 v = *(const float4*)(src + q*4);
            ts[(c0+q*4+0)*65 + r] = v.x;
            ts[(c0+q*4+1)*65 + r] = v.y;
            ts[(c0+q*4+2)*65 + r] = v.z;
            ts[(c0+q*4+3)*65 + r] = v.w;
        }
    }
    __syncthreads();
    {
        const int k  = t >> 2;
        const int c0 = (t & 3) * 16;
        const size_t base = ((size_t)bn*K_ + k)*W_ + w0 + c0;
        uint32_t bh[8], bl[8];
        #pragma unroll
        for (int q = 0; q < 4; q++) {
            float4 h4, l4;
            float vv[4];
            #pragma unroll
            for (int e = 0; e < 4; e++) vv[e] = ts[k*65 + c0 + q*4 + e];
            h4.x = __uint_as_float(f2tf32(vv[0])); l4.x = __uint_as_float(f2tf32(vv[0] - h4.x));
            h4.y = __uint_as_float(f2tf32(vv[1])); l4.y = __uint_as_float(f2tf32(vv[1] - h4.y));
            h4.z = __uint_as_float(f2tf32(vv[2])); l4.z = __uint_as_float(f2tf32(vv[2] - h4.z));
            h4.w = __uint_as_float(f2tf32(vv[3])); l4.w = __uint_as_float(f2tf32(vv[3] - h4.w));
            *(float4*)(g_PThi + base + q*4) = h4;
            *(float4*)(g_PTlo + base + q*4) = l4;
            split_bf16x2(vv[0], vv[1], bh[q*2+0], bl[q*2+0]);
            split_bf16x2(vv[2], vv[3], bh[q*2+1], bl[q*2+1]);
        }
        *(uint4*)(g_PTbh + base)     = *(uint4*)&bh[0];
        *(uint4*)(g_PTbh + base + 8) = *(uint4*)&bh[4];
        *(uint4*)(g_PTbl + base)     = *(uint4*)&bl[0];
        *(uint4*)(g_PTbl + base + 8) = *(uint4*)&bl[4];
    }
}

// ---------------------------------------------------------------------------
// HMMA bf16x3 GEMM (unchanged)
// ---------------------------------------------------------------------------
#define PITCH 72
#define MG_SMEM (4 * 128 * PITCH * 2)

template<int MODE>
__global__ __launch_bounds__(256)
void mma_gemm(const float* __restrict__ bias, float* __restrict__ out) {
    extern __shared__ __align__(16) __nv_bfloat16 sb[];
    __nv_bfloat16* Ash = sb;
    __nv_bfloat16* Asl = sb + 128*PITCH;
    __nv_bfloat16* Bsh = sb + 2*128*PITCH;
    __nv_bfloat16* Bsl = sb + 3*128*PITCH;
    const int tid = threadIdx.x, lane = tid & 31, wid = tid >> 5;
    const int wm = wid >> 2, wn = wid & 3;
    const int r0 = blockIdx.y*128, c0 = blockIdx.x*128;

    float acc[4][4][4] = {};

    for (int k0 = 0; k0 < C_; k0 += 64) {
        #pragma unroll
        for (int s = 0; s < 4; s++) {
            const int idx = tid + s*256;
            const int row = idx >> 3, q = idx & 7;
            const size_t ga = (size_t)(r0 + row)*C_ + k0 + q*8;
            const size_t gb = (size_t)(c0 + row)*C_ + k0 + q*8;
            *(uint4*)&Ash[row*PITCH + q*8] = *(const uint4*)(g_Ahi + ga);
            *(uint4*)&Asl[row*PITCH + q*8] = *(const uint4*)(g_Alo + ga);
            *(uint4*)&Bsh[row*PITCH + q*8] = *(const uint4*)(g_Bhi + gb);
            *(uint4*)&Bsl[row*PITCH + q*8] = *(const uint4*)(g_Blo + gb);
        }
        __syncthreads();
        #pragma unroll
        for (int ks = 0; ks < 4; ks++) {
            const int kk = ks * 16;
            uint32_t bh[4][2], bl[4][2];
            {
                const int row = wn*32 + (lane & 7);
                const int col = kk + ((lane >> 3) & 1) * 8;
                #pragma unroll
                for (int ni = 0; ni < 4; ni++) {
                    ldsm_x2(bh[ni], smem_u32(&Bsh[(row + ni*8)*PITCH + col]));
                    ldsm_x2(bl[ni], smem_u32(&Bsl[(row + ni*8)*PITCH + col]));
                }
            }
            #pragma unroll
            for (int mi = 0; mi < 4; mi++) {
                uint32_t ah[4], al[4];
                const int row = wm*64 + mi*16 + (lane & 15);
                const int col = kk + (lane >> 4) * 8;
                ldsm_x4(ah, smem_u32(&Ash[row*PITCH + col]));
                ldsm_x4(al, smem_u32(&Asl[row*PITCH + col]));
                #pragma unroll
                for (int ni = 0; ni < 4; ni++) {
                    mma_bf16(acc[mi][ni], ah, bh[ni]);
                    mma_bf16(acc[mi][ni], ah, bl[ni]);
                    mma_bf16(acc[mi][ni], al, bh[ni]);
                }
            }
        }
        __syncthreads();
    }

    #pragma unroll
    for (int mi = 0; mi < 4; mi++) {
        #pragma unroll
        for (int ni = 0; ni < 4; ni++) {
            #pragma unroll
            for (int h = 0; h < 2; h++) {
                const int r = r0 + wm*64 + mi*16 + (lane >> 2) + h*8;
                const int c = c0 + wn*32 + ni*8 + (lane & 3)*2;
                float2 v;
                v.x = acc[mi][ni][h*2+0] + __ldg(bias + c);
                v.y = acc[mi][ni][h*2+1] + __ldg(bias + c + 1);
                if (MODE == 0) {
                    const int bb = r >> 11, w = r & (W_-1);
                    const int n  = c >> 6,  kb = c & (K_-1);
                    *(float2*)&g_P[(((size_t)(bb*N_+n))*W_ + w)*K_ + kb] = v;
                } else {
                    *(float2*)&out[(size_t)r*C_ + c] = v;
                }
            }
        }
    }
}

// ---------------------------------------------------------------------------
// mbuild phase A / B (unchanged)
// ---------------------------------------------------------------------------
__global__ __launch_bounds__(256)
void mbuildA(const float* __restrict__ G) {
    __shared__ __align__(16) float sb[64*64];
    float* Ps = sb;
    float* Gs = sb + 2048;
    const int tx = threadIdx.x, ty = threadIdx.y;
    const int t  = ty*16 + tx;
    const int bn = blockIdx.y, ch = blockIdx.x;
    const int n  = bn & (N_-1);
    const float* Pp = g_P + (size_t)bn*W_*K_;
    const float* Gp = G   + (size_t)n *W_*K_;

    float m[4][4] = {};
    for (int w0 = ch*256; w0 < ch*256 + 256; w0 += 32) {
        #pragma unroll
        for (int s = 0; s < 2; s++) {
            const int i4 = t + s*256;
            ((float4*)Ps)[i4] = ((const float4*)(Pp + (size_t)w0*K_))[i4];
            ((float4*)Gs)[i4] = ((const float4*)(Gp + (size_t)w0*K_))[i4];
        }
        __syncthreads();
        #pragma unroll 8
        for (int ww = 0; ww < 32; ww++) {
            float a[4];
            #pragma unroll
            for (int i = 0; i < 4; i++) a[i] = Ps[ww*64 + ty*4 + i];
            const float4 b4 = *(const float4*)&Gs[ww*64 + tx*4];
            const float b[4] = {b4.x, b4.y, b4.z, b4.w};
            #pragma unroll
            for (int i = 0; i < 4; i++)
                #pragma unroll
                for (int j = 0; j < 4; j++)
                    m[i][j] = fmaf(a[i], b[j], m[i][j]);
        }
        __syncthreads();
    }
    float* dst = g_Mp + ((size_t)bn*8 + ch)*4096;
    #pragma unroll
    for (int i = 0; i < 4; i++)
        #pragma unroll
        for (int j = 0; j < 4; j++)
            dst[(ty*4+i)*64 + tx*4 + j] = m[i][j];
}

__global__ __launch_bounds__(256)
void mbuildB() {
    __shared__ float sb[64*65];
    const int tx = threadIdx.x, ty = threadIdx.y;
    const int bn = blockIdx.x;
    float m[4][4] = {};
    const float* src = g_Mp + (size_t)bn*8*4096;
    #pragma unroll
    for (int ch = 0; ch < 8; ch++)
        #pragma unroll
        for (int i = 0; i < 4; i++)
            #pragma unroll
            for (int j = 0; j < 4; j++)
                m[i][j] += src[ch*4096 + (ty*4+i)*64 + tx*4 + j];
    #pragma unroll
    for (int i = 0; i < 4; i++)
        #pragma unroll
        for (int j = 0; j < 4; j++)
            if (tx*4 + j > ty*4 + i) m[i][j] = 0.f;
    #pragma unroll
    for (int i = 0; i < 4; i++)
        #pragma unroll
        for (int j = 0; j < 4; j++)
            sb[(ty*4+i)*65 + tx*4 + j] = m[i][j];
    __syncthreads();
    float mm[4][4] = {};
    #pragma unroll 8
    for (int jj = 0; jj < 64; jj++) {
        float a[4], b[4];
        #pragma unroll
        for (int i = 0; i < 4; i++) a[i] = sb[(ty*4+i)*65 + jj];
        #pragma unroll
        for (int j = 0; j < 4; j++) b[j] = sb[(tx*4+j)*65 + jj];
        #pragma unroll
        for (int i = 0; i < 4; i++)
            #pragma unroll
            for (int j = 0; j < 4; j++)
                mm[i][j] = fmaf(a[i], b[j], mm[i][j]);
    }
    #pragma unroll
    for (int i = 0; i < 4; i++)
        #pragma unroll
        for (int j = 0; j < 4; j++)
            g_M[(size_t)bn*K_*K_ + (ty*4+i)*K_ + tx*4 + j] = mm[i][j];
}

// ---------------------------------------------------------------------------
// Flash attention, tensor-core edition; K/V tiles are pure vector copies
// from the pre-split transposed buffers.
// ---------------------------------------------------------------------------
#define QP 68
#define KP 72
#define FL_SMEM 124928

__global__ __launch_bounds__(256)
void flash_kernel() {
    extern __shared__ __align__(16) float fsm[];
    float* Qh = fsm;                 // 128*68
    float* Ql = fsm + 8704;
    float* Kh = fsm + 17408;         // 64*72
    float* Kl = fsm + 22016;
    __nv_bfloat16* Vh = (__nv_bfloat16*)(fsm + 26624);   // 64*72 bf16
    __nv_bfloat16* Vl = (__nv_bfloat16*)(fsm + 28928);

    const int t = threadIdx.x;
    const int lane = t & 31, wid = t >> 5;
    const int bn = blockIdx.y;
    const int b = bn >> 4, n = bn & 15;
    const int qt = 15 - (int)blockIdx.x;
    const int w0 = qt * 128;
    const float* Pp = g_P + (size_t)bn*W_*K_;
    const float* Mp = g_M + (size_t)bn*K_*K_;

    // ---- Prologue: Pq -> Qh (flat), M -> Kh, compute Qm, split to Qh/Ql ----
    #pragma unroll
    for (int s = 0; s < 8; s++) {
        const int i4 = t + s*256;
        ((float4*)Qh)[i4] = ((const float4*)(Pp + (size_t)w0*K_))[i4];
    }
    #pragma unroll
    for (int s = 0; s < 16; s++) {
        const int idx = t + s*256;
        Kh[(idx >> 6)*KP + (idx & 63)] = Mp[idx];
    }
    __syncthreads();
    {
        const int trow = t >> 4, tcol = t & 15;
        int R[8];
        #pragma unroll
        for (int i = 0; i < 8; i++) R[i] = (i < 4) ? trow*4 + i : 64 + trow*4 + (i-4);
        float q[8][4] = {};
        #pragma unroll 4
        for (int kk = 0; kk < 64; kk++) {
            float a[8], bb[4];
            #pragma unroll
            for (int i = 0; i < 8; i++) a[i] = Qh[R[i]*64 + kk];
            #pragma unroll
            for (int j = 0; j < 4; j++) bb[j] = Kh[kk*KP + tcol*4 + j];
            #pragma unroll
            for (int i = 0; i < 8; i++)
                #pragma unroll
                for (int j = 0; j < 4; j++)
                    q[i][j] = fmaf(a[i], bb[j], q[i][j]);
        }
        __syncthreads();
        #pragma unroll
        for (int i = 0; i < 8; i++)
            #pragma unroll
            for (int j = 0; j < 4; j++) {
                const float v = q[i][j];
                const float fh = __uint_as_float(f2tf32(v));
                Qh[R[i]*QP + tcol*4 + j] = fh;
                Ql[R[i]*QP + tcol*4 + j] = __uint_as_float(f2tf32(v - fh));
            }
    }

    const int qrow = wid * 16;
    const int q0 = w0 + qrow + (lane >> 2);
    const int q1 = q0 + 8;
    float mrun0 = -INFINITY, mrun1 = -INFINITY, lrun0 = 0.f, lrun1 = 0.f;
    float oacc[8][4] = {};

    for (int v0 = 0; v0 <= w0 + 64; v0 += 64) {
        __syncthreads();
        // ---- K/V tile: vector copies from pre-split buffers ----
        {
            const int d  = t >> 2;
            const int c0 = (t & 3) * 16;
            const size_t base = ((size_t)bn*K_ + d)*W_ + v0 + c0;
            #pragma unroll
            for (int q = 0; q < 4; q++) {
                *(float4*)&Kh[d*KP + c0 + q*4] = *(const float4*)(g_PThi + base + q*4);
                *(float4*)&Kl[d*KP + c0 + q*4] = *(const float4*)(g_PTlo + base + q*4);
            }
            *(uint4*)&Vh[d*KP + c0]     = *(const uint4*)(g_PTbh + base);
            *(uint4*)&Vh[d*KP + c0 + 8] = *(const uint4*)(g_PTbh + base + 8);
            *(uint4*)&Vl[d*KP + c0]     = *(const uint4*)(g_PTbl + base);
            *(uint4*)&Vl[d*KP + c0 + 8] = *(const uint4*)(g_PTbl + base + 8);
        }
        __syncthreads();

        if (v0 <= w0 + qrow + 15) {
            // ---- GEMM1: S = Qm @ K^T (3xTF32) ----
            float sacc[8][4] = {};
            #pragma unroll
            for (int ks = 0; ks < 8; ks++) {
                uint32_t ah[4], al[4];
                const int ar0 = qrow + (lane >> 2), ar1 = ar0 + 8;
                const int ac  = ks*8 + (lane & 3);
                ah[0] = *(uint32_t*)&Qh[ar0*QP + ac];
                ah[1] = *(uint32_t*)&Qh[ar1*QP + ac];
                ah[2] = *(uint32_t*)&Qh[ar0*QP + ac + 4];
                ah[3] = *(uint32_t*)&Qh[ar1*QP + ac + 4];
                al[0] = *(uint32_t*)&Ql[ar0*QP + ac];
                al[1] = *(uint32_t*)&Ql[ar1*QP + ac];
                al[2] = *(uint32_t*)&Ql[ar0*QP + ac + 4];
                al[3] = *(uint32_t*)&Ql[ar1*QP + ac + 4];
                #pragma unroll
                for (int nt = 0; nt < 8; nt++) {
                    uint32_t bh[2], bl[2];
                    const int bc = nt*8 + (lane >> 2);
                    const int br = ks*8 + (lane & 3);
                    bh[0] = *(uint32_t*)&Kh[br*KP + bc];
                    bh[1] = *(uint32_t*)&Kh[(br+4)*KP + bc];
                    bl[0] = *(uint32_t*)&Kl[br*KP + bc];
                    bl[1] = *(uint32_t*)&Kl[(br+4)*KP + bc];
                    mma_tf32(sacc[nt], ah, bl);
                    mma_tf32(sacc[nt], al, bh);
                    mma_tf32(sacc[nt], ah, bh);
                }
            }
            // ---- softmax (registers only) ----
            const bool dm = (v0 + 63 > w0 + qrow);
            float mx0 = -INFINITY, mx1 = -INFINITY;
            #pragma unroll
            for (int nt = 0; nt < 8; nt++)
                #pragma unroll
                for (int j = 0; j < 2; j++) {
                    const int key = v0 + nt*8 + (lane & 3)*2 + j;
                    float s0 = sacc[nt][j]   * 0.125f;
                    float s1 = sacc[nt][2+j] * 0.125f;
                    if (dm && key > q0) s0 = -INFINITY;
                    if (dm && key > q1) s1 = -INFINITY;
                    sacc[nt][j] = s0; sacc[nt][2+j] = s1;
                    mx0 = fmaxf(mx0, s0); mx1 = fmaxf(mx1, s1);
                }
            mx0 = fmaxf(mx0, __shfl_xor_sync(0xffffffffu, mx0, 1));
            mx0 = fmaxf(mx0, __shfl_xor_sync(0xffffffffu, mx0, 2));
            mx1 = fmaxf(mx1, __shfl_xor_sync(0xffffffffu, mx1, 1));
            mx1 = fmaxf(mx1, __shfl_xor_sync(0xffffffffu, mx1, 2));
            const float mn0 = fmaxf(mrun0, mx0), mn1 = fmaxf(mrun1, mx1);
            const float al0 = __expf(mrun0 - mn0), al1 = __expf(mrun1 - mn1);
            float sum0 = 0.f, sum1 = 0.f;
            #pragma unroll
            for (int nt = 0; nt < 8; nt++)
                #pragma unroll
                for (int j = 0; j < 2; j++) {
                    const float p0 = __expf(sacc[nt][j]   - mn0);
                    const float p1 = __expf(sacc[nt][2+j] - mn1);
                    sacc[nt][j] = p0; sacc[nt][2+j] = p1;
                    sum0 += p0; sum1 += p1;
                }
            sum0 += __shfl_xor_sync(0xffffffffu, sum0, 1);
            sum0 += __shfl_xor_sync(0xffffffffu, sum0, 2);
            sum1 += __shfl_xor_sync(0xffffffffu, sum1, 1);
            sum1 += __shfl_xor_sync(0xffffffffu, sum1, 2);
            lrun0 = lrun0*al0 + sum0; lrun1 = lrun1*al1 + sum1;
            mrun0 = mn0; mrun1 = mn1;
            #pragma unroll
            for (int dt = 0; dt < 8; dt++) {
                oacc[dt][0] *= al0; oacc[dt][1] *= al0;
                oacc[dt][2] *= al1; oacc[dt][3] *= al1;
            }
            // ---- GEMM2: O += P~ @ V (bf16x3, A from registers) ----
            #pragma unroll
            for (int s4 = 0; s4 < 4; s4++) {
                uint32_t ah[4], al[4];
                split_bf16x2(sacc[2*s4][0],   sacc[2*s4][1],   ah[0], al[0]);
                split_bf16x2(sacc[2*s4][2],   sacc[2*s4][3],   ah[1], al[1]);
                split_bf16x2(sacc[2*s4+1][0], sacc[2*s4+1][1], ah[2], al[2]);
                split_bf16x2(sacc[2*s4+1][2], sacc[2*s4+1][3], ah[3], al[3]);
                const int col = s4*16 + ((lane >> 3) & 1) * 8;
                #pragma unroll
                for (int dt = 0; dt < 8; dt++) {
                    uint32_t bh[2], bl[2];
                    const int row = dt*8 + (lane & 7);
                    ldsm_x2(bh, smem_u32(&Vh[row*KP + col]));
                    ldsm_x2(bl, smem_u32(&Vl[row*KP + col]));
                    mma_bf16(oacc[dt], ah, bh);
                    mma_bf16(oacc[dt], ah, bl);
                    mma_bf16(oacc[dt], al, bh);
                }
            }
        }
    }
    // ---- Epilogue ----
    const float inv0 = 1.0f / lrun0, inv1 = 1.0f / lrun1;
    #pragma unroll
    for (int dt = 0; dt < 8; dt++) {
        const int c = n*K_ + dt*8 + (lane & 3)*2;
        *(float2*)&g_Ng[((size_t)(b*W_ + q0))*C_ + c] =
            make_float2(oacc[dt][0]*inv0, oacc[dt][1]*inv0);
        *(float2*)&g_Ng[((size_t)(b*W_ + q1))*C_ + c] =
            make_float2(oacc[dt][2]*inv1, oacc[dt][3]*inv1);
    }
}

// ---------------------------------------------------------------------------
extern "C" void kernel_launch(void* const* d_in, const int* in_sizes, int n_in,
                              void* d_out, int out_size) {
    const float* x  = (const float*)d_in[0];
    const float* Wp = (const float*)d_in[1];
    const float* bp = (const float*)d_in[2];
    const float* G  = (const float*)d_in[3];
    const float* Wm = (const float*)d_in[4];
    const float* bm = (const float*)d_in[5];
    float* out = (float*)d_out;

    cudaFuncSetAttribute(flash_kernel, cudaFuncAttributeMaxDynamicSharedMemorySize, FL_SMEM);
    cudaFuncSetAttribute(mma_gemm<0>, cudaFuncAttributeMaxDynamicSharedMemorySize, MG_SMEM);
    cudaFuncSetAttribute(mma_gemm<1>, cudaFuncAttributeMaxDynamicSharedMemorySize, MG_SMEM);

    void *pAhi, *pAlo, *pBhi, *pBlo, *pNg;
    cudaGetSymbolAddress(&pAhi, g_Ahi);
    cudaGetSymbolAddress(&pAlo, g_Alo);
    cudaGetSymbolAddress(&pBhi, g_Bhi);
    cudaGetSymbolAddress(&pBlo, g_Blo);
    cudaGetSymbolAddress(&pNg,  g_Ng);

    const int nA4 = (B_*W_*C_) / 4;
    const int nW4 = (C_*C_) / 4;
    dim3 blk(16, 16);

    convert_kernel<<<nA4/256, 256>>>(x,  (__nv_bfloat16*)pAhi, (__nv_bfloat16*)pAlo, nA4);
    convert_kernel<<<nW4/256, 256>>>(Wp, (__nv_bfloat16*)pBhi, (__nv_bfloat16*)pBlo, nW4);
    mma_gemm<0><<<dim3(8, 32), 256, MG_SMEM>>>(bp, nullptr);
    prep_kernel<<<dim3(32, 32), 256>>>();
    mbuildA<<<dim3(8, 32), blk>>>(G);
    mbuildB<<<32, blk>>>();
    flash_kernel<<<dim3(16, 32), 256, FL_SMEM>>>();
    convert_kernel<<<nA4/256, 256>>>((const float*)pNg, (__nv_bfloat16*)pAhi, (__nv_bfloat16*)pAlo, nA4);
    convert_kernel<<<nW4/256, 256>>>(Wm, (__nv_bfloat16*)pBhi, (__nv_bfloat16*)pBlo, nW4);
    mma_gemm<1><<<dim3(8, 32), 256, MG_SMEM>>>(bm, out);
}

// round 8
// speedup vs baseline: 1.0527x; 1.0527x over previous
#include <cuda_runtime.h>
#include <cuda_bf16.h>
#include <math.h>
#include <cstdint>

#define B_ 2
#define W_ 2048
#define C_ 1024
#define N_ 16
#define K_ 64
#define HEADS (B_*N_)

__device__ float g_P [B_*N_*W_*K_];     // P in [b][n][w][k] layout
__device__ float g_M [HEADS*K_*K_];     // mm per head
__device__ float g_Mp[HEADS*8*K_*K_];   // mbuild partials
__device__ float g_Ng[B_*W_*C_];        // nudged in [b][w][c] layout

__device__ __nv_bfloat16 g_Ahi[(size_t)B_*W_*C_];
__device__ __nv_bfloat16 g_Alo[(size_t)B_*W_*C_];
__device__ __nv_bfloat16 g_Bhi[(size_t)C_*C_];
__device__ __nv_bfloat16 g_Blo[(size_t)C_*C_];

// P transposed per head [head][k][w], pre-split once (prep_kernel)
__device__ float         g_PThi[(size_t)HEADS*K_*W_];
__device__ float         g_PTlo[(size_t)HEADS*K_*W_];
__device__ __nv_bfloat16 g_PTbh[(size_t)HEADS*K_*W_];
__device__ __nv_bfloat16 g_PTbl[(size_t)HEADS*K_*W_];

// ---------------- helpers (plain sm_80-class PTX only) ----------------
__device__ __forceinline__ uint32_t smem_u32(const void* p) {
    uint32_t a;
    asm("{ .reg .u64 t; cvta.to.shared.u64 t, %1; cvt.u32.u64 %0, t; }" : "=r"(a) : "l"(p));
    return a;
}
__device__ __forceinline__ void ldsm_x4(uint32_t* r, uint32_t addr) {
    asm volatile("ldmatrix.sync.aligned.m8n8.x4.shared.b16 {%0,%1,%2,%3}, [%4];"
        : "=r"(r[0]), "=r"(r[1]), "=r"(r[2]), "=r"(r[3]) : "r"(addr));
}
__device__ __forceinline__ void ldsm_x2(uint32_t* r, uint32_t addr) {
    asm volatile("ldmatrix.sync.aligned.m8n8.x2.shared.b16 {%0,%1}, [%2];"
        : "=r"(r[0]), "=r"(r[1]) : "r"(addr));
}
__device__ __forceinline__ void mma_bf16(float* d, const uint32_t* a, const uint32_t* b) {
    asm volatile("mma.sync.aligned.m16n8k16.row.col.f32.bf16.bf16.f32 "
        "{%0,%1,%2,%3}, {%4,%5,%6,%7}, {%8,%9}, {%0,%1,%2,%3};"
        : "+f"(d[0]), "+f"(d[1]), "+f"(d[2]), "+f"(d[3])
        : "r"(a[0]), "r"(a[1]), "r"(a[2]), "r"(a[3]), "r"(b[0]), "r"(b[1]));
}
__device__ __forceinline__ void mma_tf32(float* d, const uint32_t* a, const uint32_t* b) {
    asm volatile("mma.sync.aligned.m16n8k8.row.col.f32.tf32.tf32.f32 "
        "{%0,%1,%2,%3}, {%4,%5,%6,%7}, {%8,%9}, {%0,%1,%2,%3};"
        : "+f"(d[0]), "+f"(d[1]), "+f"(d[2]), "+f"(d[3])
        : "r"(a[0]), "r"(a[1]), "r"(a[2]), "r"(a[3]), "r"(b[0]), "r"(b[1]));
}
__device__ __forceinline__ uint32_t f2tf32(float f) {
    uint32_t u; asm("cvt.rna.tf32.f32 %0, %1;" : "=r"(u) : "f"(f)); return u;
}
__device__ __forceinline__ void split_bf16x2(float x, float y, uint32_t& h, uint32_t& l) {
    __nv_bfloat16 hx = __float2bfloat16(x), hy = __float2bfloat16(y);
    __nv_bfloat16 lx = __float2bfloat16(x - __bfloat162float(hx));
    __nv_bfloat16 ly = __float2bfloat16(y - __bfloat162float(hy));
    __nv_bfloat162 hh = __halves2bfloat162(hx, hy);
    __nv_bfloat162 ll = __halves2bfloat162(lx, ly);
    h = *(uint32_t*)&hh; l = *(uint32_t*)&ll;
}
#define CP16(sa, gp) asm volatile("cp.async.cg.shared.global [%0], [%1], 16;" :: "r"(sa), "l"(gp))
#define CP_COMMIT()  asm volatile("cp.async.commit_group;")
#define CP_WAIT0()   asm volatile("cp.async.wait_group 0;")
#define CP_WAIT1()   asm volatile("cp.async.wait_group 1;")

// ---------------------------------------------------------------------------
__global__ __launch_bounds__(256)
void convert_kernel(const float* __restrict__ src, __nv_bfloat16* __restrict__ hi,
                    __nv_bfloat16* __restrict__ lo, int n4) {
    const int i = blockIdx.x * blockDim.x + threadIdx.x;
    if (i >= n4) return;
    const float4 v = ((const float4*)src)[i];
    uint32_t h0, l0, h1, l1;
    split_bf16x2(v.x, v.y, h0, l0);
    split_bf16x2(v.z, v.w, h1, l1);
    ((uint32_t*)hi)[i*2+0] = h0; ((uint32_t*)hi)[i*2+1] = h1;
    ((uint32_t*)lo)[i*2+0] = l0; ((uint32_t*)lo)[i*2+1] = l1;
}

// ---------------------------------------------------------------------------
// prep: transpose P [w][k] -> [k][w] per head, split tf32 hi/lo + bf16 hi/lo
// ---------------------------------------------------------------------------
__global__ __launch_bounds__(256)
void prep_kernel() {
    __shared__ __align__(16) float ts[64*65];
    const int t = threadIdx.x;
    const int bn = blockIdx.y;
    const int w0 = blockIdx.x * 64;
    const float* Pp = g_P + (size_t)bn*W_*K_;
    {
        const int r  = t >> 2;
        const int c0 = (t & 3) * 16;
        const float* src = Pp + (size_t)(w0 + r)*K_ + c0;
        #pragma unroll
        for (int q = 0; q < 4; q++) {
            const float4 v = *(const float4*)(src + q*4);
            ts[(c0+q*4+0)*65 + r] = v.x;
            ts[(c0+q*4+1)*65 + r] = v.y;
            ts[(c0+q*4+2)*65 + r] = v.z;
            ts[(c0+q*4+3)*65 + r] = v.w;
        }
    }
    __syncthreads();
    {
        const int k  = t >> 2;
        const int c0 = (t & 3) * 16;
        const size_t base = ((size_t)bn*K_ + k)*W_ + w0 + c0;
        uint32_t bh[8], bl[8];
        #pragma unroll
        for (int q = 0; q < 4; q++) {
            float4 h4, l4;
            float vv[4];
            #pragma unroll
            for (int e = 0; e < 4; e++) vv[e] = ts[k*65 + c0 + q*4 + e];
            h4.x = __uint_as_float(f2tf32(vv[0])); l4.x = __uint_as_float(f2tf32(vv[0] - h4.x));
            h4.y = __uint_as_float(f2tf32(vv[1])); l4.y = __uint_as_float(f2tf32(vv[1] - h4.y));
            h4.z = __uint_as_float(f2tf32(vv[2])); l4.z = __uint_as_float(f2tf32(vv[2] - h4.z));
            h4.w = __uint_as_float(f2tf32(vv[3])); l4.w = __uint_as_float(f2tf32(vv[3] - h4.w));
            *(float4*)(g_PThi + base + q*4) = h4;
            *(float4*)(g_PTlo + base + q*4) = l4;
            split_bf16x2(vv[0], vv[1], bh[q*2+0], bl[q*2+0]);
            split_bf16x2(vv[2], vv[3], bh[q*2+1], bl[q*2+1]);
        }
        *(uint4*)(g_PTbh + base)     = *(uint4*)&bh[0];
        *(uint4*)(g_PTbh + base + 8) = *(uint4*)&bh[4];
        *(uint4*)(g_PTbl + base)     = *(uint4*)&bl[0];
        *(uint4*)(g_PTbl + base + 8) = *(uint4*)&bl[4];
    }
}

// ---------------------------------------------------------------------------
// HMMA bf16x3 GEMM (unchanged)
// ---------------------------------------------------------------------------
#define PITCH 72
#define MG_SMEM (4 * 128 * PITCH * 2)

template<int MODE>
__global__ __launch_bounds__(256)
void mma_gemm(const float* __restrict__ bias, float* __restrict__ out) {
    extern __shared__ __align__(16) __nv_bfloat16 sb[];
    __nv_bfloat16* Ash = sb;
    __nv_bfloat16* Asl = sb + 128*PITCH;
    __nv_bfloat16* Bsh = sb + 2*128*PITCH;
    __nv_bfloat16* Bsl = sb + 3*128*PITCH;
    const int tid = threadIdx.x, lane = tid & 31, wid = tid >> 5;
    const int wm = wid >> 2, wn = wid & 3;
    const int r0 = blockIdx.y*128, c0 = blockIdx.x*128;

    float acc[4][4][4] = {};

    for (int k0 = 0; k0 < C_; k0 += 64) {
        #pragma unroll
        for (int s = 0; s < 4; s++) {
            const int idx = tid + s*256;
            const int row = idx >> 3, q = idx & 7;
            const size_t ga = (size_t)(r0 + row)*C_ + k0 + q*8;
            const size_t gb = (size_t)(c0 + row)*C_ + k0 + q*8;
            *(uint4*)&Ash[row*PITCH + q*8] = *(const uint4*)(g_Ahi + ga);
            *(uint4*)&Asl[row*PITCH + q*8] = *(const uint4*)(g_Alo + ga);
            *(uint4*)&Bsh[row*PITCH + q*8] = *(const uint4*)(g_Bhi + gb);
            *(uint4*)&Bsl[row*PITCH + q*8] = *(const uint4*)(g_Blo + gb);
        }
        __syncthreads();
        #pragma unroll
        for (int ks = 0; ks < 4; ks++) {
            const int kk = ks * 16;
            uint32_t bh[4][2], bl[4][2];
            {
                const int row = wn*32 + (lane & 7);
                const int col = kk + ((lane >> 3) & 1) * 8;
                #pragma unroll
                for (int ni = 0; ni < 4; ni++) {
                    ldsm_x2(bh[ni], smem_u32(&Bsh[(row + ni*8)*PITCH + col]));
                    ldsm_x2(bl[ni], smem_u32(&Bsl[(row + ni*8)*PITCH + col]));
                }
            }
            #pragma unroll
            for (int mi = 0; mi < 4; mi++) {
                uint32_t ah[4], al[4];
                const int row = wm*64 + mi*16 + (lane & 15);
                const int col = kk + (lane >> 4) * 8;
                ldsm_x4(ah, smem_u32(&Ash[row*PITCH + col]));
                ldsm_x4(al, smem_u32(&Asl[row*PITCH + col]));
                #pragma unroll
                for (int ni = 0; ni < 4; ni++) {
                    mma_bf16(acc[mi][ni], ah, bh[ni]);
                    mma_bf16(acc[mi][ni], ah, bl[ni]);
                    mma_bf16(acc[mi][ni], al, bh[ni]);
                }
            }
        }
        __syncthreads();
    }

    #pragma unroll
    for (int mi = 0; mi < 4; mi++) {
        #pragma unroll
        for (int ni = 0; ni < 4; ni++) {
            #pragma unroll
            for (int h = 0; h < 2; h++) {
                const int r = r0 + wm*64 + mi*16 + (lane >> 2) + h*8;
                const int c = c0 + wn*32 + ni*8 + (lane & 3)*2;
                float2 v;
                v.x = acc[mi][ni][h*2+0] + __ldg(bias + c);
                v.y = acc[mi][ni][h*2+1] + __ldg(bias + c + 1);
                if (MODE == 0) {
                    const int bb = r >> 11, w = r & (W_-1);
                    const int n  = c >> 6,  kb = c & (K_-1);
                    *(float2*)&g_P[(((size_t)(bb*N_+n))*W_ + w)*K_ + kb] = v;
                } else {
                    *(float2*)&out[(size_t)r*C_ + c] = v;
                }
            }
        }
    }
}

// ---------------------------------------------------------------------------
// mbuild phase A / B (unchanged)
// ---------------------------------------------------------------------------
__global__ __launch_bounds__(256)
void mbuildA(const float* __restrict__ G) {
    __shared__ __align__(16) float sb[64*64];
    float* Ps = sb;
    float* Gs = sb + 2048;
    const int tx = threadIdx.x, ty = threadIdx.y;
    const int t  = ty*16 + tx;
    const int bn = blockIdx.y, ch = blockIdx.x;
    const int n  = bn & (N_-1);
    const float* Pp = g_P + (size_t)bn*W_*K_;
    const float* Gp = G   + (size_t)n *W_*K_;

    float m[4][4] = {};
    for (int w0 = ch*256; w0 < ch*256 + 256; w0 += 32) {
        #pragma unroll
        for (int s = 0; s < 2; s++) {
            const int i4 = t + s*256;
            ((float4*)Ps)[i4] = ((const float4*)(Pp + (size_t)w0*K_))[i4];
            ((float4*)Gs)[i4] = ((const float4*)(Gp + (size_t)w0*K_))[i4];
        }
        __syncthreads();
        #pragma unroll 8
        for (int ww = 0; ww < 32; ww++) {
            float a[4];
            #pragma unroll
            for (int i = 0; i < 4; i++) a[i] = Ps[ww*64 + ty*4 + i];
            const float4 b4 = *(const float4*)&Gs[ww*64 + tx*4];
            const float b[4] = {b4.x, b4.y, b4.z, b4.w};
            #pragma unroll
            for (int i = 0; i < 4; i++)
                #pragma unroll
                for (int j = 0; j < 4; j++)
                    m[i][j] = fmaf(a[i], b[j], m[i][j]);
        }
        __syncthreads();
    }
    float* dst = g_Mp + ((size_t)bn*8 + ch)*4096;
    #pragma unroll
    for (int i = 0; i < 4; i++)
        #pragma unroll
        for (int j = 0; j < 4; j++)
            dst[(ty*4+i)*64 + tx*4 + j] = m[i][j];
}

__global__ __launch_bounds__(256)
void mbuildB() {
    __shared__ float sb[64*65];
    const int tx = threadIdx.x, ty = threadIdx.y;
    const int bn = blockIdx.x;
    float m[4][4] = {};
    const float* src = g_Mp + (size_t)bn*8*4096;
    #pragma unroll
    for (int ch = 0; ch < 8; ch++)
        #pragma unroll
        for (int i = 0; i < 4; i++)
            #pragma unroll
            for (int j = 0; j < 4; j++)
                m[i][j] += src[ch*4096 + (ty*4+i)*64 + tx*4 + j];
    #pragma unroll
    for (int i = 0; i < 4; i++)
        #pragma unroll
        for (int j = 0; j < 4; j++)
            if (tx*4 + j > ty*4 + i) m[i][j] = 0.f;
    #pragma unroll
    for (int i = 0; i < 4; i++)
        #pragma unroll
        for (int j = 0; j < 4; j++)
            sb[(ty*4+i)*65 + tx*4 + j] = m[i][j];
    __syncthreads();
    float mm[4][4] = {};
    #pragma unroll 8
    for (int jj = 0; jj < 64; jj++) {
        float a[4], b[4];
        #pragma unroll
        for (int i = 0; i < 4; i++) a[i] = sb[(ty*4+i)*65 + jj];
        #pragma unroll
        for (int j = 0; j < 4; j++) b[j] = sb[(tx*4+j)*65 + jj];
        #pragma unroll
        for (int i = 0; i < 4; i++)
            #pragma unroll
            for (int j = 0; j < 4; j++)
                mm[i][j] = fmaf(a[i], b[j], mm[i][j]);
    }
    #pragma unroll
    for (int i = 0; i < 4; i++)
        #pragma unroll
        for (int j = 0; j < 4; j++)
            g_M[(size_t)bn*K_*K_ + (ty*4+i)*K_ + tx*4 + j] = mm[i][j];
}

// ---------------------------------------------------------------------------
// Flash attention: tensor-core GEMMs + cp.async double-buffered K/V tiles.
// smem: Qh[128*68] Ql[128*68] then 2 x {Kh,Kl fp32 64*72; Vh,Vl bf16 64*72}.
// ---------------------------------------------------------------------------
#define QP 68
#define KP 72
#define QBYTES (2*128*QP*4)          // 69632
#define OFF_KL 18432
#define OFF_VH 36864
#define OFF_VL 46080
#define BUFSZ  55296
#define FL_SMEM (QBYTES + 2*BUFSZ)   // 180224

__global__ __launch_bounds__(256)
void flash_kernel() {
    extern __shared__ __align__(16) float fsm[];
    float* Qh = fsm;
    float* Ql = fsm + 128*QP;
    char* bufbase = (char*)fsm + QBYTES;

    const int t = threadIdx.x;
    const int lane = t & 31, wid = t >> 5;
    const int bn = blockIdx.x;
    const int b = bn >> 4, n = bn & 15;
    const int qt = 15 - (int)blockIdx.y;     // heavy-first across launch order
    const int w0 = qt * 128;
    const float* Pp = g_P + (size_t)bn*W_*K_;
    const float* Mp = g_M + (size_t)bn*K_*K_;
    const uint32_t sbase = smem_u32(fsm) + QBYTES;

    // ---- Prologue: Pq -> Qh (flat), M -> buf0 Kh area; compute Qm; split ----
    float* Mh = (float*)bufbase;
    #pragma unroll
    for (int s = 0; s < 8; s++) {
        const int i4 = t + s*256;
        ((float4*)Qh)[i4] = ((const float4*)(Pp + (size_t)w0*K_))[i4];
    }
    #pragma unroll
    for (int s = 0; s < 16; s++) {
        const int idx = t + s*256;
        Mh[(idx >> 6)*KP + (idx & 63)] = Mp[idx];
    }
    __syncthreads();
    {
        const int trow = t >> 4, tcol = t & 15;
        int R[8];
        #pragma unroll
        for (int i = 0; i < 8; i++) R[i] = (i < 4) ? trow*4 + i : 64 + trow*4 + (i-4);
        float q[8][4] = {};
        #pragma unroll 4
        for (int kk = 0; kk < 64; kk++) {
            float a[8], bb[4];
            #pragma unroll
            for (int i = 0; i < 8; i++) a[i] = Qh[R[i]*64 + kk];
            #pragma unroll
            for (int j = 0; j < 4; j++) bb[j] = Mh[kk*KP + tcol*4 + j];
            #pragma unroll
            for (int i = 0; i < 8; i++)
                #pragma unroll
                for (int j = 0; j < 4; j++)
                    q[i][j] = fmaf(a[i], bb[j], q[i][j]);
        }
        __syncthreads();   // all Mh reads done; buf0 free for cp.async
        #pragma unroll
        for (int i = 0; i < 8; i++)
            #pragma unroll
            for (int j = 0; j < 4; j++) {
                const float v = q[i][j];
                const float fh = __uint_as_float(f2tf32(v));
                Qh[R[i]*QP + tcol*4 + j] = fh;
                Ql[R[i]*QP + tcol*4 + j] = __uint_as_float(f2tf32(v - fh));
            }
    }

    // per-thread cp.async slice for one K/V tile
    const int ld_d  = t >> 2;
    const int ld_c0 = (t & 3) * 16;
    const uint32_t rowf = (uint32_t)(ld_d*KP + ld_c0) * 4;   // fp32 row offset
    const uint32_t rowb = (uint32_t)(ld_d*KP + ld_c0) * 2;   // bf16 row offset

    #define ISSUE_TILE(v0_, bi_) do {                                             \
        const size_t base_ = ((size_t)bn*K_ + ld_d)*W_ + (v0_) + ld_c0;           \
        const uint32_t bb_ = sbase + (bi_)*BUFSZ;                                 \
        CP16(bb_ + rowf,      g_PThi + base_);                                    \
        CP16(bb_ + rowf + 16, g_PThi + base_ + 4);                                \
        CP16(bb_ + rowf + 32, g_PThi + base_ + 8);                                \
        CP16(bb_ + rowf + 48, g_PThi + base_ + 12);                               \
        CP16(bb_ + OFF_KL + rowf,      g_PTlo + base_);                           \
        CP16(bb_ + OFF_KL + rowf + 16, g_PTlo + base_ + 4);                       \
        CP16(bb_ + OFF_KL + rowf + 32, g_PTlo + base_ + 8);                       \
        CP16(bb_ + OFF_KL + rowf + 48, g_PTlo + base_ + 12);                      \
        CP16(bb_ + OFF_VH + rowb,      g_PTbh + base_);                           \
        CP16(bb_ + OFF_VH + rowb + 16, g_PTbh + base_ + 8);                       \
        CP16(bb_ + OFF_VL + rowb,      g_PTbl + base_);                           \
        CP16(bb_ + OFF_VL + rowb + 16, g_PTbl + base_ + 8);                       \
        CP_COMMIT();                                                              \
    } while (0)

    ISSUE_TILE(0, 0);

    const int qrow = wid * 16;
    const int q0 = w0 + qrow + (lane >> 2);
    const int q1 = q0 + 8;
    float mrun0 = -INFINITY, mrun1 = -INFINITY, lrun0 = 0.f, lrun1 = 0.f;
    float oacc[8][4] = {};
    const int last = w0 + 64;

    for (int v0 = 0; v0 <= last; v0 += 64) {
        const int bi = (v0 >> 6) & 1;
        __syncthreads();    // iter0: Qh/Ql split visible; later: buf[bi^1] readers done
        if (v0 + 64 <= last) {
            ISSUE_TILE(v0 + 64, bi ^ 1);
            CP_WAIT1();
        } else {
            CP_WAIT0();
        }
        __syncthreads();    // current buffer complete for ALL threads
        char* bp = bufbase + bi*BUFSZ;
        float* Kh = (float*)bp;
        float* Kl = (float*)(bp + OFF_KL);
        __nv_bfloat16* Vh = (__nv_bfloat16*)(bp + OFF_VH);
        __nv_bfloat16* Vl = (__nv_bfloat16*)(bp + OFF_VL);

        if (v0 <= w0 + qrow + 15) {
            // ---- GEMM1: S = Qm @ K^T (3xTF32) ----
            float sacc[8][4] = {};
            #pragma unroll
            for (int ks = 0; ks < 8; ks++) {
                uint32_t ah[4], al[4];
                const int ar0 = qrow + (lane >> 2), ar1 = ar0 + 8;
                const int ac  = ks*8 + (lane & 3);
                ah[0] = *(uint32_t*)&Qh[ar0*QP + ac];
                ah[1] = *(uint32_t*)&Qh[ar1*QP + ac];
                ah[2] = *(uint32_t*)&Qh[ar0*QP + ac + 4];
                ah[3] = *(uint32_t*)&Qh[ar1*QP + ac + 4];
                al[0] = *(uint32_t*)&Ql[ar0*QP + ac];
                al[1] = *(uint32_t*)&Ql[ar1*QP + ac];
                al[2] = *(uint32_t*)&Ql[ar0*QP + ac + 4];
                al[3] = *(uint32_t*)&Ql[ar1*QP + ac + 4];
                #pragma unroll
                for (int nt = 0; nt < 8; nt++) {
                    uint32_t bh[2], bl[2];
                    const int bc = nt*8 + (lane >> 2);
                    const int br = ks*8 + (lane & 3);
                    bh[0] = *(uint32_t*)&Kh[br*KP + bc];
                    bh[1] = *(uint32_t*)&Kh[(br+4)*KP + bc];
                    bl[0] = *(uint32_t*)&Kl[br*KP + bc];
                    bl[1] = *(uint32_t*)&Kl[(br+4)*KP + bc];
                    mma_tf32(sacc[nt], ah, bl);
                    mma_tf32(sacc[nt], al, bh);
                    mma_tf32(sacc[nt], ah, bh);
                }
            }
            // ---- softmax (registers only) ----
            const bool dm = (v0 + 63 > w0 + qrow);
            float mx0 = -INFINITY, mx1 = -INFINITY;
            #pragma unroll
            for (int nt = 0; nt < 8; nt++)
                #pragma unroll
                for (int j = 0; j < 2; j++) {
                    const int key = v0 + nt*8 + (lane & 3)*2 + j;
                    float s0 = sacc[nt][j]   * 0.125f;
                    float s1 = sacc[nt][2+j] * 0.125f;
                    if (dm && key > q0) s0 = -INFINITY;
                    if (dm && key > q1) s1 = -INFINITY;
                    sacc[nt][j] = s0; sacc[nt][2+j] = s1;
                    mx0 = fmaxf(mx0, s0); mx1 = fmaxf(mx1, s1);
                }
            mx0 = fmaxf(mx0, __shfl_xor_sync(0xffffffffu, mx0, 1));
            mx0 = fmaxf(mx0, __shfl_xor_sync(0xffffffffu, mx0, 2));
            mx1 = fmaxf(mx1, __shfl_xor_sync(0xffffffffu, mx1, 1));
            mx1 = fmaxf(mx1, __shfl_xor_sync(0xffffffffu, mx1, 2));
            const float mn0 = fmaxf(mrun0, mx0), mn1 = fmaxf(mrun1, mx1);
            const float al0 = __expf(mrun0 - mn0), al1 = __expf(mrun1 - mn1);
            float sum0 = 0.f, sum1 = 0.f;
            #pragma unroll
            for (int nt = 0; nt < 8; nt++)
                #pragma unroll
                for (int j = 0; j < 2; j++) {
                    const float p0 = __expf(sacc[nt][j]   - mn0);
                    const float p1 = __expf(sacc[nt][2+j] - mn1);
                    sacc[nt][j] = p0; sacc[nt][2+j] = p1;
                    sum0 += p0; sum1 += p1;
                }
            sum0 += __shfl_xor_sync(0xffffffffu, sum0, 1);
            sum0 += __shfl_xor_sync(0xffffffffu, sum0, 2);
            sum1 += __shfl_xor_sync(0xffffffffu, sum1, 1);
            sum1 += __shfl_xor_sync(0xffffffffu, sum1, 2);
            lrun0 = lrun0*al0 + sum0; lrun1 = lrun1*al1 + sum1;
            mrun0 = mn0; mrun1 = mn1;
            #pragma unroll
            for (int dt = 0; dt < 8; dt++) {
                oacc[dt][0] *= al0; oacc[dt][1] *= al0;
                oacc[dt][2] *= al1; oacc[dt][3] *= al1;
            }
            // ---- GEMM2: O += P~ @ V (bf16x3, A from registers) ----
            #pragma unroll
            for (int s4 = 0; s4 < 4; s4++) {
                uint32_t ah[4], al[4];
                split_bf16x2(sacc[2*s4][0],   sacc[2*s4][1],   ah[0], al[0]);
                split_bf16x2(sacc[2*s4][2],   sacc[2*s4][3],   ah[1], al[1]);
                split_bf16x2(sacc[2*s4+1][0], sacc[2*s4+1][1], ah[2], al[2]);
                split_bf16x2(sacc[2*s4+1][2], sacc[2*s4+1][3], ah[3], al[3]);
                const int col = s4*16 + ((lane >> 3) & 1) * 8;
                #pragma unroll
                for (int dt = 0; dt < 8; dt++) {
                    uint32_t bh[2], bl[2];
                    const int row = dt*8 + (lane & 7);
                    ldsm_x2(bh, smem_u32(&Vh[row*KP + col]));
                    ldsm_x2(bl, smem_u32(&Vl[row*KP + col]));
                    mma_bf16(oacc[dt], ah, bh);
                    mma_bf16(oacc[dt], ah, bl);
                    mma_bf16(oacc[dt], al, bh);
                }
            }
        }
    }
    // ---- Epilogue ----
    const float inv0 = 1.0f / lrun0, inv1 = 1.0f / lrun1;
    #pragma unroll
    for (int dt = 0; dt < 8; dt++) {
        const int c = n*K_ + dt*8 + (lane & 3)*2;
        *(float2*)&g_Ng[((size_t)(b*W_ + q0))*C_ + c] =
            make_float2(oacc[dt][0]*inv0, oacc[dt][1]*inv0);
        *(float2*)&g_Ng[((size_t)(b*W_ + q1))*C_ + c] =
            make_float2(oacc[dt][2]*inv1, oacc[dt][3]*inv1);
    }
    #undef ISSUE_TILE
}

// ---------------------------------------------------------------------------
extern "C" void kernel_launch(void* const* d_in, const int* in_sizes, int n_in,
                              void* d_out, int out_size) {
    const float* x  = (const float*)d_in[0];
    const float* Wp = (const float*)d_in[1];
    const float* bp = (const float*)d_in[2];
    const float* G  = (const float*)d_in[3];
    const float* Wm = (const float*)d_in[4];
    const float* bm = (const float*)d_in[5];
    float* out = (float*)d_out;

    cudaFuncSetAttribute(flash_kernel, cudaFuncAttributeMaxDynamicSharedMemorySize, FL_SMEM);
    cudaFuncSetAttribute(mma_gemm<0>, cudaFuncAttributeMaxDynamicSharedMemorySize, MG_SMEM);
    cudaFuncSetAttribute(mma_gemm<1>, cudaFuncAttributeMaxDynamicSharedMemorySize, MG_SMEM);

    void *pAhi, *pAlo, *pBhi, *pBlo, *pNg;
    cudaGetSymbolAddress(&pAhi, g_Ahi);
    cudaGetSymbolAddress(&pAlo, g_Alo);
    cudaGetSymbolAddress(&pBhi, g_Bhi);
    cudaGetSymbolAddress(&pBlo, g_Blo);
    cudaGetSymbolAddress(&pNg,  g_Ng);

    const int nA4 = (B_*W_*C_) / 4;
    const int nW4 = (C_*C_) / 4;
    dim3 blk(16, 16);

    convert_kernel<<<nA4/256, 256>>>(x,  (__nv_bfloat16*)pAhi, (__nv_bfloat16*)pAlo, nA4);
    convert_kernel<<<nW4/256, 256>>>(Wp, (__nv_bfloat16*)pBhi, (__nv_bfloat16*)pBlo, nW4);
    mma_gemm<0><<<dim3(8, 32), 256, MG_SMEM>>>(bp, nullptr);
    prep_kernel<<<dim3(32, 32), 256>>>();
    mbuildA<<<dim3(8, 32), blk>>>(G);
    mbuildB<<<32, blk>>>();
    flash_kernel<<<dim3(32, 16), 256, FL_SMEM>>>();
    convert_kernel<<<nA4/256, 256>>>((const float*)pNg, (__nv_bfloat16*)pAhi, (__nv_bfloat16*)pAlo, nA4);
    convert_kernel<<<nW4/256, 256>>>(Wm, (__nv_bfloat16*)pBhi, (__nv_bfloat16*)pBlo, nW4);
    mma_gemm<1><<<dim3(8, 32), 256, MG_SMEM>>>(bm, out);
}

// round 9
// speedup vs baseline: 1.3516x; 1.2840x over previous
#include <cuda_runtime.h>
#include <cuda_bf16.h>
#include <math.h>
#include <cstdint>

#define B_ 2
#define W_ 2048
#define C_ 1024
#define N_ 16
#define K_ 64
#define HEADS (B_*N_)

__device__ float g_P [B_*N_*W_*K_];     // P in [b][n][w][k] layout
__device__ float g_M [HEADS*K_*K_];     // mm per head
__device__ float g_Mp[HEADS*8*K_*K_];   // mbuild partials
__device__ float g_Ng[B_*W_*C_];        // nudged in [b][w][c] layout

__device__ __nv_bfloat16 g_Ahi[(size_t)B_*W_*C_];
__device__ __nv_bfloat16 g_Alo[(size_t)B_*W_*C_];
__device__ __nv_bfloat16 g_Bhi[(size_t)C_*C_];
__device__ __nv_bfloat16 g_Blo[(size_t)C_*C_];

// K operand, fragment-paired: [head][ks(8)][w][dm(4)][4] floats,
// vec = {tf32hi(d), tf32hi(d+4), tf32lo(d), tf32lo(d+4)}, d = ks*8+dm
__device__ float         g_PTq[(size_t)HEADS*8*W_*16];
// V operand transposed [head][d][w], bf16 hi/lo
__device__ __nv_bfloat16 g_PTbh[(size_t)HEADS*K_*W_];
__device__ __nv_bfloat16 g_PTbl[(size_t)HEADS*K_*W_];

// ---------------- helpers (plain sm_80-class PTX only) ----------------
__device__ __forceinline__ uint32_t smem_u32(const void* p) {
    uint32_t a;
    asm("{ .reg .u64 t; cvta.to.shared.u64 t, %1; cvt.u32.u64 %0, t; }" : "=r"(a) : "l"(p));
    return a;
}
__device__ __forceinline__ void ldsm_x4(uint32_t* r, uint32_t addr) {
    asm volatile("ldmatrix.sync.aligned.m8n8.x4.shared.b16 {%0,%1,%2,%3}, [%4];"
        : "=r"(r[0]), "=r"(r[1]), "=r"(r[2]), "=r"(r[3]) : "r"(addr));
}
__device__ __forceinline__ void ldsm_x2(uint32_t* r, uint32_t addr) {
    asm volatile("ldmatrix.sync.aligned.m8n8.x2.shared.b16 {%0,%1}, [%2];"
        : "=r"(r[0]), "=r"(r[1]) : "r"(addr));
}
__device__ __forceinline__ void mma_bf16(float* d, const uint32_t* a, const uint32_t* b) {
    asm volatile("mma.sync.aligned.m16n8k16.row.col.f32.bf16.bf16.f32 "
        "{%0,%1,%2,%3}, {%4,%5,%6,%7}, {%8,%9}, {%0,%1,%2,%3};"
        : "+f"(d[0]), "+f"(d[1]), "+f"(d[2]), "+f"(d[3])
        : "r"(a[0]), "r"(a[1]), "r"(a[2]), "r"(a[3]), "r"(b[0]), "r"(b[1]));
}
__device__ __forceinline__ void mma_tf32(float* d, const uint32_t* a, const uint32_t* b) {
    asm volatile("mma.sync.aligned.m16n8k8.row.col.f32.tf32.tf32.f32 "
        "{%0,%1,%2,%3}, {%4,%5,%6,%7}, {%8,%9}, {%0,%1,%2,%3};"
        : "+f"(d[0]), "+f"(d[1]), "+f"(d[2]), "+f"(d[3])
        : "r"(a[0]), "r"(a[1]), "r"(a[2]), "r"(a[3]), "r"(b[0]), "r"(b[1]));
}
__device__ __forceinline__ uint32_t f2tf32(float f) {
    uint32_t u; asm("cvt.rna.tf32.f32 %0, %1;" : "=r"(u) : "f"(f)); return u;
}
__device__ __forceinline__ void split_bf16x2(float x, float y, uint32_t& h, uint32_t& l) {
    __nv_bfloat16 hx = __float2bfloat16(x), hy = __float2bfloat16(y);
    __nv_bfloat16 lx = __float2bfloat16(x - __bfloat162float(hx));
    __nv_bfloat16 ly = __float2bfloat16(y - __bfloat162float(hy));
    __nv_bfloat162 hh = __halves2bfloat162(hx, hy);
    __nv_bfloat162 ll = __halves2bfloat162(lx, ly);
    h = *(uint32_t*)&hh; l = *(uint32_t*)&ll;
}
#define CP16(sa, gp) asm volatile("cp.async.cg.shared.global [%0], [%1], 16;" :: "r"(sa), "l"(gp))
#define CP_COMMIT()  asm volatile("cp.async.commit_group;")
#define CP_WAIT0()   asm volatile("cp.async.wait_group 0;")
#define CP_WAIT1()   asm volatile("cp.async.wait_group 1;")

// ---------------------------------------------------------------------------
__global__ __launch_bounds__(256)
void convert_kernel(const float* __restrict__ src, __nv_bfloat16* __restrict__ hi,
                    __nv_bfloat16* __restrict__ lo, int n4) {
    const int i = blockIdx.x * blockDim.x + threadIdx.x;
    if (i >= n4) return;
    const float4 v = ((const float4*)src)[i];
    uint32_t h0, l0, h1, l1;
    split_bf16x2(v.x, v.y, h0, l0);
    split_bf16x2(v.z, v.w, h1, l1);
    ((uint32_t*)hi)[i*2+0] = h0; ((uint32_t*)hi)[i*2+1] = h1;
    ((uint32_t*)lo)[i*2+0] = l0; ((uint32_t*)lo)[i*2+1] = l1;
}

// ---------------------------------------------------------------------------
// prep: transpose P [w][k] -> [k][w], emit fragment-paired tf32 K + bf16 V
// ---------------------------------------------------------------------------
__global__ __launch_bounds__(256)
void prep_kernel() {
    __shared__ __align__(16) float ts[64*65];
    const int t = threadIdx.x;
    const int bn = blockIdx.y;
    const int w0 = blockIdx.x * 64;
    const float* Pp = g_P + (size_t)bn*W_*K_;
    {
        const int r  = t >> 2;
        const int c0 = (t & 3) * 16;
        const float* src = Pp + (size_t)(w0 + r)*K_ + c0;
        #pragma unroll
        for (int q = 0; q < 4; q++) {
            const float4 v = *(const float4*)(src + q*4);
            ts[(c0+q*4+0)*65 + r] = v.x;
            ts[(c0+q*4+1)*65 + r] = v.y;
            ts[(c0+q*4+2)*65 + r] = v.z;
            ts[(c0+q*4+3)*65 + r] = v.w;
        }
    }
    __syncthreads();
    // bf16 V (layout [d][w])
    {
        const int k  = t >> 2;
        const int c0 = (t & 3) * 16;
        const size_t base = ((size_t)bn*K_ + k)*W_ + w0 + c0;
        uint32_t bh[8], bl[8];
        #pragma unroll
        for (int q = 0; q < 4; q++) {
            float vv[4];
            #pragma unroll
            for (int e = 0; e < 4; e++) vv[e] = ts[k*65 + c0 + q*4 + e];
            split_bf16x2(vv[0], vv[1], bh[q*2+0], bl[q*2+0]);
            split_bf16x2(vv[2], vv[3], bh[q*2+1], bl[q*2+1]);
        }
        *(uint4*)(g_PTbh + base)     = *(uint4*)&bh[0];
        *(uint4*)(g_PTbh + base + 8) = *(uint4*)&bh[4];
        *(uint4*)(g_PTbl + base)     = *(uint4*)&bl[0];
        *(uint4*)(g_PTbl + base + 8) = *(uint4*)&bl[4];
    }
    // tf32 fragment-paired K
    #pragma unroll
    for (int p = 0; p < 8; p++) {
        const int id = t + p*256;          // (ks, w, dm)
        const int dm = id & 3, w = (id >> 2) & 63, ks = id >> 8;
        const float v0 = ts[(ks*8 + dm)*65 + w];
        const float v4 = ts[(ks*8 + dm + 4)*65 + w];
        float4 o;
        o.x = __uint_as_float(f2tf32(v0));
        o.y = __uint_as_float(f2tf32(v4));
        o.z = __uint_as_float(f2tf32(v0 - o.x));
        o.w = __uint_as_float(f2tf32(v4 - o.y));
        *(float4*)(g_PTq + (((size_t)bn*8 + ks)*W_ + w0 + w)*16 + dm*4) = o;
    }
}

// ---------------------------------------------------------------------------
// HMMA bf16x3 GEMM with cp.async double-buffered K chunks
// ---------------------------------------------------------------------------
#define PITCH 72
#define MGBUF 73728          // Ash/Asl/Bsh/Bsl (18432 B each)
#define MG_SMEM (2*MGBUF)

template<int MODE>
__global__ __launch_bounds__(256)
void mma_gemm(const float* __restrict__ bias, float* __restrict__ out) {
    extern __shared__ __align__(16) char sbm[];
    const uint32_t sb0 = smem_u32(sbm);
    const int tid = threadIdx.x, lane = tid & 31, wid = tid >> 5;
    const int wm = wid >> 2, wn = wid & 3;
    const int r0 = blockIdx.y*128, c0 = blockIdx.x*128;

    const int ld_row = tid >> 1;           // 0..127
    const int ld_q   = (tid & 1) * 4;      // 0 or 4 (two uint4 per row half)
    // each thread copies rows ld_row, 2 uint4 pieces at q=ld_q,ld_q+... use 4 pieces:
    #define MG_ISSUE(k0_, bi_) do {                                               \
        const uint32_t bb_ = sb0 + (bi_)*MGBUF;                                   \
        _Pragma("unroll")                                                         \
        for (int s_ = 0; s_ < 4; s_++) {                                          \
            const int idx_ = tid + s_*256;                                        \
            const int row_ = idx_ >> 3, q_ = idx_ & 7;                            \
            const uint32_t so_ = (uint32_t)(row_*144 + q_*16);                    \
            const size_t ga_ = (size_t)(r0 + row_)*C_ + (k0_) + q_*8;             \
            const size_t gb_ = (size_t)(c0 + row_)*C_ + (k0_) + q_*8;             \
            CP16(bb_ + so_,          g_Ahi + ga_);                                \
            CP16(bb_ + 18432 + so_,  g_Alo + ga_);                                \
            CP16(bb_ + 36864 + so_,  g_Bhi + gb_);                                \
            CP16(bb_ + 55296 + so_,  g_Blo + gb_);                                \
        }                                                                         \
        CP_COMMIT();                                                              \
    } while (0)

    float acc[4][4][4] = {};
    MG_ISSUE(0, 0);

    for (int ch = 0; ch < 16; ch++) {
        const int bi = ch & 1;
        if (ch + 1 < 16) { MG_ISSUE((ch+1)*64, bi ^ 1); CP_WAIT1(); }
        else             { CP_WAIT0(); }
        __syncthreads();
        __nv_bfloat16* Ash = (__nv_bfloat16*)(sbm + bi*MGBUF);
        __nv_bfloat16* Asl = (__nv_bfloat16*)(sbm + bi*MGBUF + 18432);
        __nv_bfloat16* Bsh = (__nv_bfloat16*)(sbm + bi*MGBUF + 36864);
        __nv_bfloat16* Bsl = (__nv_bfloat16*)(sbm + bi*MGBUF + 55296);
        #pragma unroll
        for (int ks = 0; ks < 4; ks++) {
            const int kk = ks * 16;
            uint32_t bh[4][2], bl[4][2];
            {
                const int row = wn*32 + (lane & 7);
                const int col = kk + ((lane >> 3) & 1) * 8;
                #pragma unroll
                for (int ni = 0; ni < 4; ni++) {
                    ldsm_x2(bh[ni], smem_u32(&Bsh[(row + ni*8)*PITCH + col]));
                    ldsm_x2(bl[ni], smem_u32(&Bsl[(row + ni*8)*PITCH + col]));
                }
            }
            #pragma unroll
            for (int mi = 0; mi < 4; mi++) {
                uint32_t ah[4], al[4];
                const int row = wm*64 + mi*16 + (lane & 15);
                const int col = kk + (lane >> 4) * 8;
                ldsm_x4(ah, smem_u32(&Ash[row*PITCH + col]));
                ldsm_x4(al, smem_u32(&Asl[row*PITCH + col]));
                #pragma unroll
                for (int ni = 0; ni < 4; ni++) {
                    mma_bf16(acc[mi][ni], ah, bh[ni]);
                    mma_bf16(acc[mi][ni], ah, bl[ni]);
                    mma_bf16(acc[mi][ni], al, bh[ni]);
                }
            }
        }
        __syncthreads();
    }
    #undef MG_ISSUE
    (void)ld_row; (void)ld_q;

    #pragma unroll
    for (int mi = 0; mi < 4; mi++) {
        #pragma unroll
        for (int ni = 0; ni < 4; ni++) {
            #pragma unroll
            for (int h = 0; h < 2; h++) {
                const int r = r0 + wm*64 + mi*16 + (lane >> 2) + h*8;
                const int c = c0 + wn*32 + ni*8 + (lane & 3)*2;
                float2 v;
                v.x = acc[mi][ni][h*2+0] + __ldg(bias + c);
                v.y = acc[mi][ni][h*2+1] + __ldg(bias + c + 1);
                if (MODE == 0) {
                    const int bb = r >> 11, w = r & (W_-1);
                    const int n  = c >> 6,  kb = c & (K_-1);
                    *(float2*)&g_P[(((size_t)(bb*N_+n))*W_ + w)*K_ + kb] = v;
                } else {
                    *(float2*)&out[(size_t)r*C_ + c] = v;
                }
            }
        }
    }
}

// ---------------------------------------------------------------------------
// mbuild phase A / B (unchanged)
// ---------------------------------------------------------------------------
__global__ __launch_bounds__(256)
void mbuildA(const float* __restrict__ G) {
    __shared__ __align__(16) float sb[64*64];
    float* Ps = sb;
    float* Gs = sb + 2048;
    const int tx = threadIdx.x, ty = threadIdx.y;
    const int t  = ty*16 + tx;
    const int bn = blockIdx.y, ch = blockIdx.x;
    const int n  = bn & (N_-1);
    const float* Pp = g_P + (size_t)bn*W_*K_;
    const float* Gp = G   + (size_t)n *W_*K_;

    float m[4][4] = {};
    for (int w0 = ch*256; w0 < ch*256 + 256; w0 += 32) {
        #pragma unroll
        for (int s = 0; s < 2; s++) {
            const int i4 = t + s*256;
            ((float4*)Ps)[i4] = ((const float4*)(Pp + (size_t)w0*K_))[i4];
            ((float4*)Gs)[i4] = ((const float4*)(Gp + (size_t)w0*K_))[i4];
        }
        __syncthreads();
        #pragma unroll 8
        for (int ww = 0; ww < 32; ww++) {
            float a[4];
            #pragma unroll
            for (int i = 0; i < 4; i++) a[i] = Ps[ww*64 + ty*4 + i];
            const float4 b4 = *(const float4*)&Gs[ww*64 + tx*4];
            const float b[4] = {b4.x, b4.y, b4.z, b4.w};
            #pragma unroll
            for (int i = 0; i < 4; i++)
                #pragma unroll
                for (int j = 0; j < 4; j++)
                    m[i][j] = fmaf(a[i], b[j], m[i][j]);
        }
        __syncthreads();
    }
    float* dst = g_Mp + ((size_t)bn*8 + ch)*4096;
    #pragma unroll
    for (int i = 0; i < 4; i++)
        #pragma unroll
        for (int j = 0; j < 4; j++)
            dst[(ty*4+i)*64 + tx*4 + j] = m[i][j];
}

__global__ __launch_bounds__(256)
void mbuildB() {
    __shared__ float sb[64*65];
    const int tx = threadIdx.x, ty = threadIdx.y;
    const int bn = blockIdx.x;
    float m[4][4] = {};
    const float* src = g_Mp + (size_t)bn*8*4096;
    #pragma unroll
    for (int ch = 0; ch < 8; ch++)
        #pragma unroll
        for (int i = 0; i < 4; i++)
            #pragma unroll
            for (int j = 0; j < 4; j++)
                m[i][j] += src[ch*4096 + (ty*4+i)*64 + tx*4 + j];
    #pragma unroll
    for (int i = 0; i < 4; i++)
        #pragma unroll
        for (int j = 0; j < 4; j++)
            if (tx*4 + j > ty*4 + i) m[i][j] = 0.f;
    #pragma unroll
    for (int i = 0; i < 4; i++)
        #pragma unroll
        for (int j = 0; j < 4; j++)
            sb[(ty*4+i)*65 + tx*4 + j] = m[i][j];
    __syncthreads();
    float mm[4][4] = {};
    #pragma unroll 8
    for (int jj = 0; jj < 64; jj++) {
        float a[4], b[4];
        #pragma unroll
        for (int i = 0; i < 4; i++) a[i] = sb[(ty*4+i)*65 + jj];
        #pragma unroll
        for (int j = 0; j < 4; j++) b[j] = sb[(tx*4+j)*65 + jj];
        #pragma unroll
        for (int i = 0; i < 4; i++)
            #pragma unroll
            for (int j = 0; j < 4; j++)
                mm[i][j] = fmaf(a[i], b[j], mm[i][j]);
    }
    #pragma unroll
    for (int i = 0; i < 4; i++)
        #pragma unroll
        for (int j = 0; j < 4; j++)
            g_M[(size_t)bn*K_*K_ + (ty*4+i)*K_ + tx*4 + j] = mm[i][j];
}

// ---------------------------------------------------------------------------
// Flash attention: A-frags in registers, LDS.128 B-frags, cp.async K/V tiles.
// Buffer: Kq fp32 [8ks][64key][4dm][4] = 32768 B; Vh/Vl bf16 64x72 = 9216 each.
// ---------------------------------------------------------------------------
#define QP 68
#define KP 72
#define QBYTES (2*128*QP*4)          // 69632
#define OFF_VH 32768
#define OFF_VL 41984
#define BUFSZ  51200
#define FL_SMEM (QBYTES + 2*BUFSZ)   // 172032

__global__ __launch_bounds__(256)
void flash_kernel() {
    extern __shared__ __align__(16) float fsm[];
    float* Qh = fsm;
    float* Ql = fsm + 128*QP;
    char* bufbase = (char*)fsm + QBYTES;

    const int t = threadIdx.x;
    const int lane = t & 31, wid = t >> 5;
    const int bn = blockIdx.x;
    const int b = bn >> 4, n = bn & 15;
    const int qt = 15 - (int)blockIdx.y;
    const int w0 = qt * 128;
    const float* Pp = g_P + (size_t)bn*W_*K_;
    const float* Mp = g_M + (size_t)bn*K_*K_;
    const uint32_t sbase = smem_u32(fsm) + QBYTES;

    // ---- Prologue ----
    float* Mh = (float*)bufbase;     // M staged in buf0 (freed before tile0 lands)
    #pragma unroll
    for (int s = 0; s < 8; s++) {
        const int i4 = t + s*256;
        ((float4*)Qh)[i4] = ((const float4*)(Pp + (size_t)w0*K_))[i4];
    }
    #pragma unroll
    for (int s = 0; s < 16; s++) {
        const int idx = t + s*256;
        Mh[(idx >> 6)*KP + (idx & 63)] = Mp[idx];
    }
    __syncthreads();
    {
        const int trow = t >> 4, tcol = t & 15;
        int R[8];
        #pragma unroll
        for (int i = 0; i < 8; i++) R[i] = (i < 4) ? trow*4 + i : 64 + trow*4 + (i-4);
        float q[8][4] = {};
        #pragma unroll 4
        for (int kk = 0; kk < 64; kk++) {
            float a[8], bb[4];
            #pragma unroll
            for (int i = 0; i < 8; i++) a[i] = Qh[R[i]*64 + kk];
            #pragma unroll
            for (int j = 0; j < 4; j++) bb[j] = Mh[kk*KP + tcol*4 + j];
            #pragma unroll
            for (int i = 0; i < 8; i++)
                #pragma unroll
                for (int j = 0; j < 4; j++)
                    q[i][j] = fmaf(a[i], bb[j], q[i][j]);
        }
        __syncthreads();   // Mh reads done; Qh flat reads done
        #pragma unroll
        for (int i = 0; i < 8; i++)
            #pragma unroll
            for (int j = 0; j < 4; j++) {
                const float v = q[i][j];
                const float fh = __uint_as_float(f2tf32(v));
                Qh[R[i]*QP + tcol*4 + j] = fh;
                Ql[R[i]*QP + tcol*4 + j] = __uint_as_float(f2tf32(v - fh));
            }
    }
    __syncthreads();       // split visible to all warps

    // ---- A-fragments to registers (loop-invariant) ----
    const int qrow = wid * 16;
    uint32_t AH[8][4], AL[8][4];
    {
        const int ar0 = qrow + (lane >> 2), ar1 = ar0 + 8;
        #pragma unroll
        for (int ks = 0; ks < 8; ks++) {
            const int ac = ks*8 + (lane & 3);
            AH[ks][0] = *(uint32_t*)&Qh[ar0*QP + ac];
            AH[ks][1] = *(uint32_t*)&Qh[ar1*QP + ac];
            AH[ks][2] = *(uint32_t*)&Qh[ar0*QP + ac + 4];
            AH[ks][3] = *(uint32_t*)&Qh[ar1*QP + ac + 4];
            AL[ks][0] = *(uint32_t*)&Ql[ar0*QP + ac];
            AL[ks][1] = *(uint32_t*)&Ql[ar1*QP + ac];
            AL[ks][2] = *(uint32_t*)&Ql[ar0*QP + ac + 4];
            AL[ks][3] = *(uint32_t*)&Ql[ar1*QP + ac + 4];
        }
    }

    // per-thread cp.async slice
    const int ld_d  = t >> 2;
    const int ld_c0 = (t & 3) * 16;
    const uint32_t rowb = (uint32_t)(ld_d*KP + ld_c0) * 2;

    #define ISSUE_TILE(v0_, bi_) do {                                             \
        const uint32_t bb_ = sbase + (bi_)*BUFSZ;                                 \
        _Pragma("unroll")                                                         \
        for (int p_ = 0; p_ < 8; p_++) {                                          \
            const int id_ = t + p_*256;                                           \
            const int ks_ = id_ >> 8;                                             \
            CP16(bb_ + (uint32_t)id_*16,                                          \
                 g_PTq + (((size_t)bn*8 + ks_)*W_ + (v0_))*16 + (id_ & 255)*4);   \
        }                                                                         \
        const size_t vb_ = ((size_t)bn*K_ + ld_d)*W_ + (v0_) + ld_c0;             \
        CP16(bb_ + OFF_VH + rowb,      g_PTbh + vb_);                             \
        CP16(bb_ + OFF_VH + rowb + 16, g_PTbh + vb_ + 8);                         \
        CP16(bb_ + OFF_VL + rowb,      g_PTbl + vb_);                             \
        CP16(bb_ + OFF_VL + rowb + 16, g_PTbl + vb_ + 8);                         \
        CP_COMMIT();                                                              \
    } while (0)

    ISSUE_TILE(0, 0);

    const int q0 = w0 + qrow + (lane >> 2);
    const int q1 = q0 + 8;
    float mrun0 = -INFINITY, mrun1 = -INFINITY, lrun0 = 0.f, lrun1 = 0.f;
    float oacc[8][4] = {};
    const int last = w0 + 64;

    for (int v0 = 0; v0 <= last; v0 += 64) {
        const int bi = (v0 >> 6) & 1;
        if (v0 + 64 <= last) { ISSUE_TILE(v0 + 64, bi ^ 1); CP_WAIT1(); }
        else                 { CP_WAIT0(); }
        __syncthreads();
        char* bp = bufbase + bi*BUFSZ;
        float* Kq = (float*)bp;
        __nv_bfloat16* Vh = (__nv_bfloat16*)(bp + OFF_VH);
        __nv_bfloat16* Vl = (__nv_bfloat16*)(bp + OFF_VL);

        if (v0 <= w0 + qrow + 15) {
            // ---- GEMM1: S = Qm @ K^T (3xTF32, B via single LDS.128) ----
            float sacc[8][4] = {};
            const int keyl = lane >> 2, dml = lane & 3;
            #pragma unroll
            for (int ks = 0; ks < 8; ks++) {
                #pragma unroll
                for (int nt = 0; nt < 8; nt++) {
                    const float4 bq = *(const float4*)&Kq[((ks*64 + nt*8 + keyl)*4 + dml)*4];
                    uint32_t bh[2] = {__float_as_uint(bq.x), __float_as_uint(bq.y)};
                    uint32_t bl[2] = {__float_as_uint(bq.z), __float_as_uint(bq.w)};
                    mma_tf32(sacc[nt], AH[ks], bl);
                    mma_tf32(sacc[nt], AL[ks], bh);
                    mma_tf32(sacc[nt], AH[ks], bh);
                }
            }
            // ---- softmax (registers only) ----
            const bool dm = (v0 + 63 > w0 + qrow);
            float mx0 = -INFINITY, mx1 = -INFINITY;
            #pragma unroll
            for (int nt = 0; nt < 8; nt++)
                #pragma unroll
                for (int j = 0; j < 2; j++) {
                    const int key = v0 + nt*8 + (lane & 3)*2 + j;
                    float s0 = sacc[nt][j]   * 0.125f;
                    float s1 = sacc[nt][2+j] * 0.125f;
                    if (dm && key > q0) s0 = -INFINITY;
                    if (dm && key > q1) s1 = -INFINITY;
                    sacc[nt][j] = s0; sacc[nt][2+j] = s1;
                    mx0 = fmaxf(mx0, s0); mx1 = fmaxf(mx1, s1);
                }
            mx0 = fmaxf(mx0, __shfl_xor_sync(0xffffffffu, mx0, 1));
            mx0 = fmaxf(mx0, __shfl_xor_sync(0xffffffffu, mx0, 2));
            mx1 = fmaxf(mx1, __shfl_xor_sync(0xffffffffu, mx1, 1));
            mx1 = fmaxf(mx1, __shfl_xor_sync(0xffffffffu, mx1, 2));
            const float mn0 = fmaxf(mrun0, mx0), mn1 = fmaxf(mrun1, mx1);
            const float al0 = __expf(mrun0 - mn0), al1 = __expf(mrun1 - mn1);
            float sum0 = 0.f, sum1 = 0.f;
            #pragma unroll
            for (int nt = 0; nt < 8; nt++)
                #pragma unroll
                for (int j = 0; j < 2; j++) {
                    const float p0 = __expf(sacc[nt][j]   - mn0);
                    const float p1 = __expf(sacc[nt][2+j] - mn1);
                    sacc[nt][j] = p0; sacc[nt][2+j] = p1;
                    sum0 += p0; sum1 += p1;
                }
            sum0 += __shfl_xor_sync(0xffffffffu, sum0, 1);
            sum0 += __shfl_xor_sync(0xffffffffu, sum0, 2);
            sum1 += __shfl_xor_sync(0xffffffffu, sum1, 1);
            sum1 += __shfl_xor_sync(0xffffffffu, sum1, 2);
            lrun0 = lrun0*al0 + sum0; lrun1 = lrun1*al1 + sum1;
            mrun0 = mn0; mrun1 = mn1;
            #pragma unroll
            for (int dt = 0; dt < 8; dt++) {
                oacc[dt][0] *= al0; oacc[dt][1] *= al0;
                oacc[dt][2] *= al1; oacc[dt][3] *= al1;
            }
            // ---- GEMM2: O += P~ @ V (bf16x3, A from registers) ----
            #pragma unroll
            for (int s4 = 0; s4 < 4; s4++) {
                uint32_t ah[4], al[4];
                split_bf16x2(sacc[2*s4][0],   sacc[2*s4][1],   ah[0], al[0]);
                split_bf16x2(sacc[2*s4][2],   sacc[2*s4][3],   ah[1], al[1]);
                split_bf16x2(sacc[2*s4+1][0], sacc[2*s4+1][1], ah[2], al[2]);
                split_bf16x2(sacc[2*s4+1][2], sacc[2*s4+1][3], ah[3], al[3]);
                const int col = s4*16 + ((lane >> 3) & 1) * 8;
                #pragma unroll
                for (int dt = 0; dt < 8; dt++) {
                    uint32_t bh[2], bl[2];
                    const int row = dt*8 + (lane & 7);
                    ldsm_x2(bh, smem_u32(&Vh[row*KP + col]));
                    ldsm_x2(bl, smem_u32(&Vl[row*KP + col]));
                    mma_bf16(oacc[dt], ah, bh);
                    mma_bf16(oacc[dt], ah, bl);
                    mma_bf16(oacc[dt], al, bh);
                }
            }
        }
        __syncthreads();   // all buffer reads done before it is re-filled
    }
    // ---- Epilogue ----
    const float inv0 = 1.0f / lrun0, inv1 = 1.0f / lrun1;
    #pragma unroll
    for (int dt = 0; dt < 8; dt++) {
        const int c = n*K_ + dt*8 + (lane & 3)*2;
        *(float2*)&g_Ng[((size_t)(b*W_ + q0))*C_ + c] =
            make_float2(oacc[dt][0]*inv0, oacc[dt][1]*inv0);
        *(float2*)&g_Ng[((size_t)(b*W_ + q1))*C_ + c] =
            make_float2(oacc[dt][2]*inv1, oacc[dt][3]*inv1);
    }
    #undef ISSUE_TILE
}

// ---------------------------------------------------------------------------
extern "C" void kernel_launch(void* const* d_in, const int* in_sizes, int n_in,
                              void* d_out, int out_size) {
    const float* x  = (const float*)d_in[0];
    const float* Wp = (const float*)d_in[1];
    const float* bp = (const float*)d_in[2];
    const float* G  = (const float*)d_in[3];
    const float* Wm = (const float*)d_in[4];
    const float* bm = (const float*)d_in[5];
    float* out = (float*)d_out;

    cudaFuncSetAttribute(flash_kernel, cudaFuncAttributeMaxDynamicSharedMemorySize, FL_SMEM);
    cudaFuncSetAttribute(mma_gemm<0>, cudaFuncAttributeMaxDynamicSharedMemorySize, MG_SMEM);
    cudaFuncSetAttribute(mma_gemm<1>, cudaFuncAttributeMaxDynamicSharedMemorySize, MG_SMEM);

    void *pAhi, *pAlo, *pBhi, *pBlo, *pNg;
    cudaGetSymbolAddress(&pAhi, g_Ahi);
    cudaGetSymbolAddress(&pAlo, g_Alo);
    cudaGetSymbolAddress(&pBhi, g_Bhi);
    cudaGetSymbolAddress(&pBlo, g_Blo);
    cudaGetSymbolAddress(&pNg,  g_Ng);

    const int nA4 = (B_*W_*C_) / 4;
    const int nW4 = (C_*C_) / 4;
    dim3 blk(16, 16);

    convert_kernel<<<nA4/256, 256>>>(x,  (__nv_bfloat16*)pAhi, (__nv_bfloat16*)pAlo, nA4);
    convert_kernel<<<nW4/256, 256>>>(Wp, (__nv_bfloat16*)pBhi, (__nv_bfloat16*)pBlo, nW4);
    mma_gemm<0><<<dim3(8, 32), 256, MG_SMEM>>>(bp, nullptr);
    prep_kernel<<<dim3(32, 32), 256>>>();
    mbuildA<<<dim3(8, 32), blk>>>(G);
    mbuildB<<<32, blk>>>();
    flash_kernel<<<dim3(32, 16), 256, FL_SMEM>>>();
    convert_kernel<<<nA4/256, 256>>>((const float*)pNg, (__nv_bfloat16*)pAhi, (__nv_bfloat16*)pAlo, nA4);
    convert_kernel<<<nW4/256, 256>>>(Wm, (__nv_bfloat16*)pBhi, (__nv_bfloat16*)pBlo, nW4);
    mma_gemm<1><<<dim3(8, 32), 256, MG_SMEM>>>(bm, out);
}